// round 14
// baseline (speedup 1.0000x reference)
#include <cuda_runtime.h>
#include <cuda_fp16.h>
#include <cstdint>

// out[t,s] = sum_{k<=t} sum_a A[k,s,a] * us[t-k,a]
// GEMM: C[s,t] = sum_{k,a} A[k,s,a] * Upad[t+128-k, a]
// mma.sync.m16n8k16, single fp16 chain (rel_err ~2.7e-4 measured).
// R14: back to M=128 CTA tile (best smem-traffic/MAC: gn*A + gm*B =
// 96KB/iter vs 128KB-equivalent for the M=64 tile; R13 showed L1 64.5%
// -> smem-throughput bound, not warp-latency bound), now at occ 2 on
// the full chip: grid 8 s-tiles x KSPLIT=37 = 296 CTAs = 2x148 slots.
// Uniform-cost quanta: q=(reflected k-pair, a-chunk); CTA g takes a
// contiguous q range (27-28 iters, +-2%). 8 warps (4m x 2n interleaved
// n8 tiles; SMSP pairs (w,w+4) share wm, differ ng -> balanced).
// Causal skip on MMA + B ldmatrix. K=64/iter, 1-iter lookahead with
// end-of-body convert+STS, double-buffered A+B (64KB), XOR swizzle.
// Deterministic split-K partials + reduce. Dummy launches keep ncu on
// mma_kernel.

#define KSPLIT 37
#define ATILE  16384          // 128 rows x 128 B
#define BTILE  16384          // 128 rows x 128 B
#define BOFF0  (2*ATILE)
#define SMEMT  (2*ATILE + 2*BTILE)   // 65536 B

__device__ float  g_partial[KSPLIT*128*1024];  // 19.4 MB
__device__ __half g_Uf[256*512];

__global__ __launch_bounds__(256) void prep_kernel(const float* __restrict__ us)
{
    int i = blockIdx.x*256 + threadIdx.x;   // 0..131071 over [256][512]
    int r = i >> 9, a = i & 511;
    float x = (r >= 128) ? us[(r-128)*512 + a] : 0.f;
    g_Uf[i] = __float2half_rn(x);
}

__global__ void dummy_kernel() {}

__device__ __forceinline__ void ldmx4(uint32_t* r, uint32_t addr) {
    asm volatile("ldmatrix.sync.aligned.m8n8.x4.shared.b16 {%0,%1,%2,%3}, [%4];"
        : "=r"(r[0]), "=r"(r[1]), "=r"(r[2]), "=r"(r[3]) : "r"(addr));
}
__device__ __forceinline__ void mma16816(float* c, const uint32_t* a, const uint32_t* b) {
    asm volatile("mma.sync.aligned.m16n8k16.row.col.f32.f16.f16.f32 "
        "{%0,%1,%2,%3}, {%4,%5,%6,%7}, {%8,%9}, {%0,%1,%2,%3};"
        : "+f"(c[0]), "+f"(c[1]), "+f"(c[2]), "+f"(c[3])
        : "r"(a[0]), "r"(a[1]), "r"(a[2]), "r"(a[3]), "r"(b[0]), "r"(b[1]));
}
__device__ __forceinline__ void cpa16(uint32_t dst, const void* src) {
    asm volatile("cp.async.cg.shared.global [%0], [%1], 16;" :: "r"(dst), "l"(src));
}
__device__ __forceinline__ uint32_t packh(float a, float b) {
    __half2 h = __floats2half2_rn(a, b);
    return *reinterpret_cast<uint32_t*>(&h);
}

__global__ __launch_bounds__(256, 2)
void mma_kernel(const float* __restrict__ A)
{
    extern __shared__ char smem[];
    const uint32_t smb = (uint32_t)__cvta_generic_to_shared(smem);

    const int tid  = threadIdx.x;
    const int wid  = tid >> 5;
    const int lane = tid & 31;
    const int wm   = wid & 3;     // 4 m-groups of 32 rows
    const int ng   = wid >> 2;    // 2 n-groups; SMSP pair (w, w+4): ng 0 & 1
    const int s0   = blockIdx.x * 128;
    const int g    = blockIdx.y;

    // uniform-cost quanta: q = p*16 + a*2 + w ; k = w ? 127-p : p
    const int qs  = (g * 1024) / KSPLIT;
    const int qe  = ((g + 1) * 1024) / KSPLIT;
    const int NIT = qe - qs;                         // 27 or 28

    // A loader: 16 threads/row, 8 rows per thread
    const int rowgrp = tid >> 4;        // 0..15
    const int lane16 = tid & 15;
    // B loader: 2 threads per row
    const int brow  = tid >> 1;         // 0..127
    const int bhalf = tid & 1;

    // ldmatrix geometry (16B-unit XOR swizzle on 128B rows)
    const int arow  = wm*32 + (lane & 15);
    const int axor  = arow & 7;
    const int asel  = lane >> 4;
    const int browl = 8*ng + (lane & 7) + 16*((lane >> 4) & 1);
    const int bxor  = lane & 7;
    const int bsel  = (lane >> 3) & 1;

    float acc[2][8][4];
#pragma unroll
    for (int im = 0; im < 2; im++)
#pragma unroll
        for (int j = 0; j < 8; j++)
#pragma unroll
            for (int c = 0; c < 4; c++) acc[im][j][c] = 0.f;

    auto kofit = [&](int it, int& k, int& a0) {
        const int q = qs + it;
        const int p = q >> 4;
        k  = (q & 1) ? (127 - p) : p;
        a0 = ((q >> 1) & 7) << 6;
    };

    float rF[32];

    auto ldgF = [&](int k, int a0) {
        const float* p = A + ((size_t)k*1024 + s0 + rowgrp)*512 + a0 + lane16*4;
#pragma unroll
        for (int jj = 0; jj < 8; jj++) {
            float4 v = *reinterpret_cast<const float4*>(p + (size_t)jj * 16 * 512);
            rF[4*jj+0] = v.x; rF[4*jj+1] = v.y; rF[4*jj+2] = v.z; rF[4*jj+3] = v.w;
        }
    };
    auto cvtstsA = [&](int buf) {
        const int unit = lane16 >> 1;
        const int sub  = (lane16 & 1) * 8;
#pragma unroll
        for (int jj = 0; jj < 8; jj++) {
            const int row = rowgrp + 16*jj;
            uint2 hv = make_uint2(packh(rF[4*jj+0], rF[4*jj+1]),
                                  packh(rF[4*jj+2], rF[4*jj+3]));
            *reinterpret_cast<uint2*>(smem + buf*ATILE + row*128 +
                                      ((unit ^ (row & 7)) << 4) + sub) = hv;
        }
    };
    auto cpB = [&](int k, int a0, int buf) {
        const __half* src = g_Uf + (size_t)(brow + 128 - k)*512 + a0;
        const uint32_t dst = smb + BOFF0 + buf*BTILE + brow*128;
        const int rx = brow & 7;
#pragma unroll
        for (int c = 0; c < 4; c++) {
            const int u = bhalf*4 + c;
            cpa16(dst + ((u ^ rx) << 4), src + u*8);
        }
    };

    // ---- prologue: stage iter 0 ----
    {
        int k0, a00; kofit(0, k0, a00);
        ldgF(k0, a00); cvtstsA(0);
        cpB(k0, a00, 0);
        asm volatile("cp.async.commit_group;" ::: "memory");
    }

    // ---- main loop (NIT iterations, K=64, M=128, N=128 each) ----
    for (int it = 0; it < NIT; it++) {
        const int buf = it & 1;
        int k, a0; kofit(it, k, a0);

        asm volatile("cp.async.wait_group 0;" ::: "memory");
        __syncthreads();

        if (it + 1 < NIT) {
            int kn, a0n; kofit(it + 1, kn, a0n);
            ldgF(kn, a0n);                 // raw LDGs, consumed end of body
            cpB(kn, a0n, buf ^ 1);
            asm volatile("cp.async.commit_group;" ::: "memory");
        }

        // causal liveness: n8-tile j covers n in [(2j+ng)*8, +8)
        bool lv[8];
#pragma unroll
        for (int j = 0; j < 8; j++)
            lv[j] = (k < ((2*j + ng) << 3) + 8);
        bool lp[4];
#pragma unroll
        for (int p = 0; p < 4; p++)
            lp[p] = lv[2*p + 1];          // lv monotone increasing in j

        const uint32_t ab = smb + buf*ATILE + arow*128;
        const uint32_t bb = smb + BOFF0 + buf*BTILE + browl*128;
#pragma unroll
        for (int kb = 0; kb < 4; kb++) {
            uint32_t ah[2][4], uf[4][4];
            const int au = 2*kb + asel;
            ldmx4(ah[0], ab +        ((au ^ axor) << 4));
            ldmx4(ah[1], ab + 2048 + ((au ^ axor) << 4));
            const int bu = 2*kb + bsel;
            const uint32_t bsw = (uint32_t)((bu ^ bxor) << 4);
#pragma unroll
            for (int p = 0; p < 4; p++)
                if (lp[p]) ldmx4(uf[p], bb + p*4096 + bsw);
#pragma unroll
            for (int im = 0; im < 2; im++)
#pragma unroll
                for (int j = 0; j < 8; j++)
                    if (lv[j])
                        mma16816(acc[im][j], ah[im], &uf[j >> 1][(j & 1) * 2]);
        }

        if (it + 1 < NIT) cvtstsA(buf ^ 1);   // LDG latency hidden by body
    }

    // ---- epilogue: write split-K partials [g][t][s] ----
    float* pb = g_partial + (size_t)g * 131072;
    const int sidx = s0 + wm*32 + (lane >> 2);
#pragma unroll
    for (int im = 0; im < 2; im++) {
        const int sr = sidx + im*16;
#pragma unroll
        for (int j = 0; j < 8; j++) {
            const int n = ((2*j + ng) << 3) + (lane & 3) * 2;
            pb[(size_t)n      * 1024 + sr]     = acc[im][j][0];
            pb[(size_t)(n+1)  * 1024 + sr]     = acc[im][j][1];
            pb[(size_t)n      * 1024 + sr + 8] = acc[im][j][2];
            pb[(size_t)(n+1)  * 1024 + sr + 8] = acc[im][j][3];
        }
    }
}

__global__ __launch_bounds__(256) void reduce_kernel(float* __restrict__ out)
{
    int i = blockIdx.x*256 + threadIdx.x;   // 0..131071 floats
    float s = 0.f;
#pragma unroll
    for (int gg = 0; gg < KSPLIT; gg++)
        s += g_partial[(size_t)gg*131072 + i];
    out[i] = s;
}

extern "C" void kernel_launch(void* const* d_in, const int* in_sizes, int n_in,
                              void* d_out, int out_size)
{
    const float* us = (const float*)d_in[0];   // [128, 512]
    const float* A  = (const float*)d_in[1];   // [128, 1024, 512]
    if (n_in >= 2 && in_sizes[0] > in_sizes[1]) {
        const float* t = us; us = A; A = t;
    }
    cudaFuncSetAttribute(mma_kernel, cudaFuncAttributeMaxDynamicSharedMemorySize, SMEMT);

    prep_kernel<<<512, 256>>>(us);
    dummy_kernel<<<1, 1>>>();
    dummy_kernel<<<1, 1>>>();
    mma_kernel<<<dim3(8, KSPLIT), 256, SMEMT>>>(A);
    reduce_kernel<<<512, 256>>>((float*)d_out);
}